// round 6
// baseline (speedup 1.0000x reference)
#include <cuda_runtime.h>
#include <cuda_bf16.h>
#include <cstdint>

// ---------------- problem sizes ----------------
#define TOKENS 8192
#define DMODEL 2048
#define DFF    8192

// ---------------- GEMM tiling (R5 shape — tensor pipe @96%, do not touch) ----------------
#define BM 128
#define BN 128
#define BK 64
#define STAGES 5
#define ROWB 80                         // 64B data + 16B pad: conflict-free ldmatrix
#define TILEB (128 * ROWB)              // 10240 B per operand tile
#define STAGE_BYTES (2 * TILEB)         // 20480 B
#define GEMM_SMEM (STAGES * STAGE_BYTES)// 102400 B -> 2 CTAs/SM

#define NBAND (TOKENS / BM)             // 64 row bands
#define NTILE1 (DFF / BN)               // 64 CTAs per band in gemm1

// ---------------- scratch (no allocations allowed) ----------------
__device__ int8_t g_xq [(size_t)TOKENS * DMODEL];
__device__ int8_t g_w1q[(size_t)DFF    * DMODEL];
__device__ int8_t g_w2q[(size_t)DMODEL * DFF];
__device__ int8_t g_hq [(size_t)TOKENS * DFF];
__device__ int    g_ha [(size_t)TOKENS * DFF];   // relu(acc1), exact s32
__device__ float  g_sx[TOKENS];                  // 127/absmax per token
__device__ float  g_d2[TOKENS];
__device__ int    g_rowmax[TOKENS];
__device__ int    g_bandctr[NBAND];
__device__ double g_part[2][1024];
__device__ float  g_gamma[2];

// ---------------- PTX helpers ----------------
__device__ __forceinline__ uint32_t smem_u32(const void* p) {
    uint32_t a;
    asm("{ .reg .u64 t; cvta.to.shared.u64 t, %1; cvt.u32.u64 %0, t; }" : "=r"(a) : "l"(p));
    return a;
}
#define CPA16(s, g) \
    asm volatile("cp.async.cg.shared.global [%0], [%1], 16;" :: "r"(s), "l"(g))
#define CP_COMMIT() asm volatile("cp.async.commit_group;" ::: "memory")
#define CP_WAIT3()  asm volatile("cp.async.wait_group 3;" ::: "memory")
#define LDSM4(r0, r1, r2, r3, addr) \
    asm volatile("ldmatrix.sync.aligned.m8n8.x4.shared.b16 {%0,%1,%2,%3}, [%4];" \
                 : "=r"(r0), "=r"(r1), "=r"(r2), "=r"(r3) : "r"(addr))
#define MMA_S8(c, a, b) \
    asm volatile("mma.sync.aligned.m16n8k32.row.col.s32.s8.s8.s32 " \
                 "{%0,%1,%2,%3}, {%4,%5,%6,%7}, {%8,%9}, {%0,%1,%2,%3};" \
                 : "+r"((c)[0]), "+r"((c)[1]), "+r"((c)[2]), "+r"((c)[3]) \
                 : "r"((a)[0]), "r"((a)[1]), "r"((a)[2]), "r"((a)[3]), \
                   "r"((b)[0]), "r"((b)[1]))

// ---------------- prep: quantize_x + absmean(w1) + absmean(w2) in one launch ----------------
__global__ void k_prep(const float* __restrict__ x,
                       const float* __restrict__ w1, const float* __restrict__ w2) {
    const int bx = blockIdx.x;
    if (bx < TOKENS) {
        // ---- per-token int8 quantization of x ----
        __shared__ float red[256];
        const int t = bx;
        if (t == 0 && threadIdx.x < NBAND) g_bandctr[threadIdx.x] = 0;
        const float4* row = (const float4*)(x + (size_t)t * DMODEL);
        float m = 0.f;
        for (int i = threadIdx.x; i < DMODEL / 4; i += 256) {
            float4 v = row[i];
            m = fmaxf(m, fmaxf(fmaxf(fabsf(v.x), fabsf(v.y)), fmaxf(fabsf(v.z), fabsf(v.w))));
        }
        red[threadIdx.x] = m;
        __syncthreads();
        for (int o = 128; o > 0; o >>= 1) {
            if (threadIdx.x < o) red[threadIdx.x] = fmaxf(red[threadIdx.x], red[threadIdx.x + o]);
            __syncthreads();
        }
        const float s = 127.0f / fmaxf(red[0], 1e-5f);
        char4* dst = (char4*)(g_xq + (size_t)t * DMODEL);
        for (int i = threadIdx.x; i < DMODEL / 4; i += 256) {
            float4 v = row[i];
            float q0 = fminf(fmaxf(rintf(v.x * s), -128.f), 127.f);
            float q1 = fminf(fmaxf(rintf(v.y * s), -128.f), 127.f);
            float q2 = fminf(fmaxf(rintf(v.z * s), -128.f), 127.f);
            float q3 = fminf(fmaxf(rintf(v.w * s), -128.f), 127.f);
            dst[i] = make_char4((char)(int)q0, (char)(int)q1, (char)(int)q2, (char)(int)q3);
        }
        if (threadIdx.x == 0) { g_sx[t] = s; g_rowmax[t] = 0; }
    } else {
        // ---- |w| partial sums (1024 slices per weight) ----
        __shared__ double redd[256];
        const int r = bx - TOKENS;
        const int idx = r >> 10;                  // 0: w1, 1: w2
        const int slice = r & 1023;
        const float* w = idx ? w2 : w1;
        const size_t n = (size_t)DFF * DMODEL;
        double s = 0.0;
        for (size_t i = (size_t)slice * 256 + threadIdx.x; i < n; i += (size_t)1024 * 256)
            s += (double)fabsf(w[i]);
        redd[threadIdx.x] = s;
        __syncthreads();
        for (int o = 128; o > 0; o >>= 1) {
            if (threadIdx.x < o) redd[threadIdx.x] += redd[threadIdx.x + o];
            __syncthreads();
        }
        if (threadIdx.x == 0) g_part[idx][slice] = redd[0];
    }
}

__global__ void k_finalize_gamma() {
    __shared__ double red[256];
    const int j = blockIdx.x;
    double s = 0.0;
    for (int i = threadIdx.x; i < 1024; i += 256) s += g_part[j][i];
    red[threadIdx.x] = s;
    __syncthreads();
    for (int o = 128; o > 0; o >>= 1) {
        if (threadIdx.x < o) red[threadIdx.x] += red[threadIdx.x + o];
        __syncthreads();
    }
    if (threadIdx.x == 0) {
        const double n = (double)DFF * DMODEL;
        g_gamma[j] = (float)(red[0] / n) + 1e-5f;
    }
}

// both weights ternarized in one launch (grid.y selects weight)
__global__ void k_quantize_w(const float* __restrict__ w1, const float* __restrict__ w2) {
    const int idx = blockIdx.y;
    const float* w = idx ? w2 : w1;
    int8_t* dst = idx ? g_w2q : g_w1q;
    const float g = g_gamma[idx];
    const float4* w4 = (const float4*)w;
    char4* d4 = (char4*)dst;
    const size_t n4 = (size_t)DFF * DMODEL / 4;
    for (size_t i = (size_t)blockIdx.x * blockDim.x + threadIdx.x; i < n4;
         i += (size_t)gridDim.x * blockDim.x) {
        float4 v = w4[i];
        float t0 = fminf(fmaxf(rintf(v.x / g), -1.f), 1.f);
        float t1 = fminf(fmaxf(rintf(v.y / g), -1.f), 1.f);
        float t2 = fminf(fmaxf(rintf(v.z / g), -1.f), 1.f);
        float t3 = fminf(fmaxf(rintf(v.w / g), -1.f), 1.f);
        d4[i] = make_char4((char)(int)t0, (char)(int)t1, (char)(int)t2, (char)(int)t3);
    }
}

// ---------------- int8 tensor-core GEMM ----------------
// C[BM,BN] = A[M,K] (row-major s8) * B[N,K]^T (row-major s8), s32 accum.
// 8 warps in 2x4 grid, warp tile 64x32. 5-stage cp.async pipeline, BK=64.
// MODE 1: relu(acc) -> outI + atomicMax rowmax, then the LAST CTA of each
//         128-row band requantizes the whole band into g_hq (fused quantize_h).
// MODE 0: acc * d2[row] -> outF.
template<int MODE>
__global__ void __launch_bounds__(256, 2) k_gemm(
    const int8_t* __restrict__ A, const int8_t* __restrict__ B,
    int K, int ldo,
    int* __restrict__ outI, float* __restrict__ outF,
    const float* __restrict__ d2)
{
    extern __shared__ char smem[];
    const uint32_t sbase = smem_u32(smem);
    const int t = threadIdx.x;
    const int wid = t >> 5, lane = t & 31;
    const int wm = wid >> 2, wn = wid & 3;          // 2 x 4 warp grid
    const int mBase = blockIdx.y * BM, nBase = blockIdx.x * BN;
    const int kChunks = K / BK;

    int acc[4][4][4];
    #pragma unroll
    for (int i = 0; i < 4; i++)
        #pragma unroll
        for (int j = 0; j < 4; j++)
            #pragma unroll
            for (int r = 0; r < 4; r++) acc[i][j][r] = 0;

    const int lrow = lane & 7;
    const uint32_t aOff = (uint32_t)((lrow + ((lane >> 3) & 1) * 8) * ROWB + (lane >> 4) * 16);
    const uint32_t bOff = (uint32_t)((lrow + (lane >> 4) * 8) * ROWB + ((lane >> 3) & 1) * 16);

    const int ldrow = t >> 2, ldch = t & 3;
    auto load_stage = [&](int kt, int slot) {
        const uint32_t sA = sbase + slot * STAGE_BYTES;
        const int k0 = kt * BK + ldch * 16;
        #pragma unroll
        for (int i = 0; i < 2; i++) {
            int row = ldrow + i * 64;
            CPA16(sA + row * ROWB + ldch * 16,
                  A + (size_t)(mBase + row) * K + k0);
            CPA16(sA + TILEB + row * ROWB + ldch * 16,
                  B + (size_t)(nBase + row) * K + k0);
        }
        CP_COMMIT();
    };

    load_stage(0, 0);
    load_stage(1, 1);
    load_stage(2, 2);
    load_stage(3, 3);

    for (int kt = 0; kt < kChunks; kt++) {
        CP_WAIT3();
        __syncthreads();
        const int nk = kt + 4;
        if (nk < kChunks) load_stage(nk, nk % STAGES);
        else CP_COMMIT();

        const uint32_t sA = sbase + (kt % STAGES) * STAGE_BYTES;
        const uint32_t sB = sA + TILEB;
        #pragma unroll
        for (int ks = 0; ks < 2; ks++) {
            uint32_t a[4][4], b[4][2];
            #pragma unroll
            for (int mi = 0; mi < 4; mi++)
                LDSM4(a[mi][0], a[mi][1], a[mi][2], a[mi][3],
                      sA + (wm * 64 + mi * 16) * ROWB + aOff + ks * 32);
            #pragma unroll
            for (int hf = 0; hf < 2; hf++) {
                uint32_t r0, r1, r2, r3;
                LDSM4(r0, r1, r2, r3,
                      sB + (wn * 32 + hf * 16) * ROWB + bOff + ks * 32);
                b[hf * 2][0] = r0; b[hf * 2][1] = r1;
                b[hf * 2 + 1][0] = r2; b[hf * 2 + 1][1] = r3;
            }
            #pragma unroll
            for (int mi = 0; mi < 4; mi++)
                #pragma unroll
                for (int ni = 0; ni < 4; ni++)
                    MMA_S8(acc[mi][ni], a[mi], b[ni]);
        }
    }

    // ---------------- epilogue ----------------
    #pragma unroll
    for (int mi = 0; mi < 4; mi++) {
        #pragma unroll
        for (int hf = 0; hf < 2; hf++) {
            const int row = mBase + wm * 64 + mi * 16 + hf * 8 + (lane >> 2);
            if (MODE == 1) {
                int rm = 0;
                #pragma unroll
                for (int ni = 0; ni < 4; ni++) {
                    int v0 = max(acc[mi][ni][hf * 2 + 0], 0);
                    int v1 = max(acc[mi][ni][hf * 2 + 1], 0);
                    rm = max(rm, max(v0, v1));
                    const int col = nBase + wn * 32 + ni * 8 + 2 * (lane & 3);
                    *(int2*)(outI + (size_t)row * ldo + col) = make_int2(v0, v1);
                }
                rm = max(rm, __shfl_xor_sync(0xffffffffu, rm, 1));
                rm = max(rm, __shfl_xor_sync(0xffffffffu, rm, 2));
                if ((lane & 3) == 0) atomicMax(&g_rowmax[row], rm);
            } else {
                const float s = d2[row];
                #pragma unroll
                for (int ni = 0; ni < 4; ni++) {
                    float v0 = (float)acc[mi][ni][hf * 2 + 0] * s;
                    float v1 = (float)acc[mi][ni][hf * 2 + 1] * s;
                    const int col = nBase + wn * 32 + ni * 8 + 2 * (lane & 3);
                    *(float2*)(outF + (size_t)row * ldo + col) = make_float2(v0, v1);
                }
            }
        }
    }

    if (MODE == 1) {
        // ---- fused quantize_h: last CTA of the band requantizes 128 rows ----
        __shared__ int s_last;
        __threadfence();
        __syncthreads();
        if (t == 0) s_last = (atomicAdd(&g_bandctr[blockIdx.y], 1) == NTILE1 - 1);
        __syncthreads();
        if (!s_last) return;
        __threadfence();

        __shared__ float s2row[BM], d1row[BM];
        const float gamma0 = g_gamma[0], gamma1 = g_gamma[1];
        for (int r = t; r < BM; r += 256) {
            const int tok = mBase + r;
            const float d1 = gamma0 / g_sx[tok];
            const float hl = d1 * (float)g_rowmax[tok];
            const float s2 = 127.0f / fmaxf(hl * hl, 1e-5f);
            d1row[r] = d1; s2row[r] = s2;
            g_d2[tok] = gamma1 / s2;
        }
        __syncthreads();

        const int4* src = (const int4*)(g_ha + (size_t)mBase * DFF);
        char4* dst = (char4*)(g_hq + (size_t)mBase * DFF);
        const int per_row = DFF / 4;                 // 2048 int4/char4 per row
        for (int idx = t; idx < BM * per_row; idx += 256) {
            const int r = idx / per_row;
            const float d1 = d1row[r], s2 = s2row[r];
            int4 v = src[idx];
            float a0 = (float)v.x * d1, a1 = (float)v.y * d1;
            float a2 = (float)v.z * d1, a3 = (float)v.w * d1;
            float q0 = fminf(rintf(a0 * a0 * s2), 127.f);
            float q1 = fminf(rintf(a1 * a1 * s2), 127.f);
            float q2 = fminf(rintf(a2 * a2 * s2), 127.f);
            float q3 = fminf(rintf(a3 * a3 * s2), 127.f);
            dst[idx] = make_char4((char)(int)q0, (char)(int)q1, (char)(int)q2, (char)(int)q3);
        }
    }
}

// ---------------- host ----------------
extern "C" void kernel_launch(void* const* d_in, const int* in_sizes, int n_in,
                              void* d_out, int out_size) {
    const float* x  = (const float*)d_in[0];
    const float* w1 = (const float*)d_in[1];
    const float* w2 = (const float*)d_in[2];
    float* out = (float*)d_out;

    void *p_xq, *p_w1q, *p_w2q, *p_hq, *p_ha, *p_d2;
    cudaGetSymbolAddress(&p_xq,  g_xq);
    cudaGetSymbolAddress(&p_w1q, g_w1q);
    cudaGetSymbolAddress(&p_w2q, g_w2q);
    cudaGetSymbolAddress(&p_hq,  g_hq);
    cudaGetSymbolAddress(&p_ha,  g_ha);
    cudaGetSymbolAddress(&p_d2,  g_d2);

    cudaFuncSetAttribute(k_gemm<1>, cudaFuncAttributeMaxDynamicSharedMemorySize, GEMM_SMEM);
    cudaFuncSetAttribute(k_gemm<0>, cudaFuncAttributeMaxDynamicSharedMemorySize, GEMM_SMEM);

    k_prep<<<TOKENS + 2048, 256>>>(x, w1, w2);           // 0: qx + absmean(w1,w2)
    k_finalize_gamma<<<2, 256>>>();                      // 1
    k_quantize_w<<<dim3(4096, 2), 256>>>(w1, w2);        // 2: both weights

    dim3 g1(DFF / BN, TOKENS / BM);                      // 3: 64 x 64 (fused quantize_h)
    k_gemm<1><<<g1, 256, GEMM_SMEM>>>((const int8_t*)p_xq, (const int8_t*)p_w1q,
                                      DMODEL, DFF,
                                      (int*)p_ha, nullptr, nullptr);

    dim3 g2(DMODEL / BN, TOKENS / BM);                   // 4: 16 x 64
    k_gemm<0><<<g2, 256, GEMM_SMEM>>>((const int8_t*)p_hq, (const int8_t*)p_w2q,
                                      DFF, DMODEL,
                                      nullptr, out, (const float*)p_d2);
}

// round 7
// speedup vs baseline: 1.0778x; 1.0778x over previous
#include <cuda_runtime.h>
#include <cuda_bf16.h>
#include <cstdint>

// ---------------- problem sizes ----------------
#define TOKENS 8192
#define DMODEL 2048
#define DFF    8192

// ---------------- GEMM tiling (R5 shape — tensor pipe @96%, do not touch) ----------------
#define BM 128
#define BN 128
#define BK 64
#define STAGES 5
#define ROWB 80                         // 64B data + 16B pad: conflict-free ldmatrix
#define TILEB (128 * ROWB)              // 10240 B per operand tile
#define STAGE_BYTES (2 * TILEB)         // 20480 B
#define GEMM_SMEM (STAGES * STAGE_BYTES)// 102400 B -> 2 CTAs/SM

// ---------------- scratch (no allocations allowed) ----------------
__device__ int8_t g_xq [(size_t)TOKENS * DMODEL];
__device__ int8_t g_w1q[(size_t)DFF    * DMODEL];
__device__ int8_t g_w2q[(size_t)DMODEL * DFF];
__device__ int8_t g_hq [(size_t)TOKENS * DFF];
__device__ int    g_ha [(size_t)TOKENS * DFF];   // relu(acc1), exact s32
__device__ float  g_sx[TOKENS];                  // 127/absmax per token
__device__ float  g_d2[TOKENS];
__device__ int    g_rowmax[TOKENS];
__device__ double g_part[2][1024];
__device__ float  g_gamma[2];

// ---------------- PTX helpers ----------------
__device__ __forceinline__ uint32_t smem_u32(const void* p) {
    uint32_t a;
    asm("{ .reg .u64 t; cvta.to.shared.u64 t, %1; cvt.u32.u64 %0, t; }" : "=r"(a) : "l"(p));
    return a;
}
#define CPA16(s, g) \
    asm volatile("cp.async.cg.shared.global [%0], [%1], 16;" :: "r"(s), "l"(g))
#define CP_COMMIT() asm volatile("cp.async.commit_group;" ::: "memory")
#define CP_WAIT3()  asm volatile("cp.async.wait_group 3;" ::: "memory")
#define LDSM4(r0, r1, r2, r3, addr) \
    asm volatile("ldmatrix.sync.aligned.m8n8.x4.shared.b16 {%0,%1,%2,%3}, [%4];" \
                 : "=r"(r0), "=r"(r1), "=r"(r2), "=r"(r3) : "r"(addr))
#define MMA_S8(c, a, b) \
    asm volatile("mma.sync.aligned.m16n8k32.row.col.s32.s8.s8.s32 " \
                 "{%0,%1,%2,%3}, {%4,%5,%6,%7}, {%8,%9}, {%0,%1,%2,%3};" \
                 : "+r"((c)[0]), "+r"((c)[1]), "+r"((c)[2]), "+r"((c)[3]) \
                 : "r"((a)[0]), "r"((a)[1]), "r"((a)[2]), "r"((a)[3]), \
                   "r"((b)[0]), "r"((b)[1]))

// ---------------- aux kernels ----------------
__global__ void k_quantize_x(const float* __restrict__ x) {
    __shared__ float red[256];
    const int t = blockIdx.x;
    const float4* row = (const float4*)(x + (size_t)t * DMODEL);
    float m = 0.f;
    for (int i = threadIdx.x; i < DMODEL / 4; i += 256) {
        float4 v = row[i];
        m = fmaxf(m, fmaxf(fmaxf(fabsf(v.x), fabsf(v.y)), fmaxf(fabsf(v.z), fabsf(v.w))));
    }
    red[threadIdx.x] = m;
    __syncthreads();
    for (int o = 128; o > 0; o >>= 1) {
        if (threadIdx.x < o) red[threadIdx.x] = fmaxf(red[threadIdx.x], red[threadIdx.x + o]);
        __syncthreads();
    }
    const float s = 127.0f / fmaxf(red[0], 1e-5f);
    char4* dst = (char4*)(g_xq + (size_t)t * DMODEL);
    for (int i = threadIdx.x; i < DMODEL / 4; i += 256) {
        float4 v = row[i];
        float q0 = fminf(fmaxf(rintf(v.x * s), -128.f), 127.f);
        float q1 = fminf(fmaxf(rintf(v.y * s), -128.f), 127.f);
        float q2 = fminf(fmaxf(rintf(v.z * s), -128.f), 127.f);
        float q3 = fminf(fmaxf(rintf(v.w * s), -128.f), 127.f);
        dst[i] = make_char4((char)(int)q0, (char)(int)q1, (char)(int)q2, (char)(int)q3);
    }
    if (threadIdx.x == 0) { g_sx[t] = s; g_rowmax[t] = 0; }
}

__global__ void k_absmean(const float* __restrict__ w1, const float* __restrict__ w2) {
    __shared__ double red[256];
    const int idx = blockIdx.y;
    const float* w = idx ? w2 : w1;
    const size_t n = (size_t)DFF * DMODEL;
    double s = 0.0;
    for (size_t i = (size_t)blockIdx.x * 256 + threadIdx.x; i < n; i += (size_t)gridDim.x * 256)
        s += (double)fabsf(w[i]);
    red[threadIdx.x] = s;
    __syncthreads();
    for (int o = 128; o > 0; o >>= 1) {
        if (threadIdx.x < o) red[threadIdx.x] += red[threadIdx.x + o];
        __syncthreads();
    }
    if (threadIdx.x == 0) g_part[idx][blockIdx.x] = red[0];
}

__global__ void k_finalize_gamma() {
    __shared__ double red[256];
    const int j = blockIdx.x;
    double s = 0.0;
    for (int i = threadIdx.x; i < 1024; i += 256) s += g_part[j][i];
    red[threadIdx.x] = s;
    __syncthreads();
    for (int o = 128; o > 0; o >>= 1) {
        if (threadIdx.x < o) red[threadIdx.x] += red[threadIdx.x + o];
        __syncthreads();
    }
    if (threadIdx.x == 0) {
        const double n = (double)DFF * DMODEL;
        g_gamma[j] = (float)(red[0] / n) + 1e-5f;
    }
}

__global__ void k_quantize_w(const float* __restrict__ w, int idx) {
    int8_t* dst = idx ? g_w2q : g_w1q;
    const float g = g_gamma[idx];
    const float4* w4 = (const float4*)w;
    char4* d4 = (char4*)dst;
    const size_t n4 = (size_t)DFF * DMODEL / 4;
    for (size_t i = (size_t)blockIdx.x * blockDim.x + threadIdx.x; i < n4;
         i += (size_t)gridDim.x * blockDim.x) {
        float4 v = w4[i];
        float t0 = fminf(fmaxf(rintf(v.x / g), -1.f), 1.f);
        float t1 = fminf(fmaxf(rintf(v.y / g), -1.f), 1.f);
        float t2 = fminf(fmaxf(rintf(v.z / g), -1.f), 1.f);
        float t3 = fminf(fmaxf(rintf(v.w / g), -1.f), 1.f);
        d4[i] = make_char4((char)(int)t0, (char)(int)t1, (char)(int)t2, (char)(int)t3);
    }
}

__global__ void k_quantize_h() {
    const int t = blockIdx.x;
    const float d1 = g_gamma[0] / g_sx[t];
    const float hl = d1 * (float)g_rowmax[t];
    const float s2 = 127.0f / fmaxf(hl * hl, 1e-5f);
    const int4* src = (const int4*)(g_ha + (size_t)t * DFF);
    char4* dst = (char4*)(g_hq + (size_t)t * DFF);
    for (int i = threadIdx.x; i < DFF / 4; i += blockDim.x) {
        int4 v = src[i];
        float a0 = (float)v.x * d1, a1 = (float)v.y * d1;
        float a2 = (float)v.z * d1, a3 = (float)v.w * d1;
        float q0 = fminf(rintf(a0 * a0 * s2), 127.f);
        float q1 = fminf(rintf(a1 * a1 * s2), 127.f);
        float q2 = fminf(rintf(a2 * a2 * s2), 127.f);
        float q3 = fminf(rintf(a3 * a3 * s2), 127.f);
        dst[i] = make_char4((char)(int)q0, (char)(int)q1, (char)(int)q2, (char)(int)q3);
    }
    if (threadIdx.x == 0) g_d2[t] = g_gamma[1] / s2;
}

// ---------------- int8 tensor-core GEMM (R5, unchanged) ----------------
template<int MODE>
__global__ void __launch_bounds__(256, 2) k_gemm(
    const int8_t* __restrict__ A, const int8_t* __restrict__ B,
    int K, int ldo,
    int* __restrict__ outI, float* __restrict__ outF,
    int* __restrict__ rowmax, const float* __restrict__ d2)
{
    extern __shared__ char smem[];
    const uint32_t sbase = smem_u32(smem);
    const int t = threadIdx.x;
    const int wid = t >> 5, lane = t & 31;
    const int wm = wid >> 2, wn = wid & 3;          // 2 x 4 warp grid
    const int mBase = blockIdx.y * BM, nBase = blockIdx.x * BN;
    const int kChunks = K / BK;

    int acc[4][4][4];
    #pragma unroll
    for (int i = 0; i < 4; i++)
        #pragma unroll
        for (int j = 0; j < 4; j++)
            #pragma unroll
            for (int r = 0; r < 4; r++) acc[i][j][r] = 0;

    const int lrow = lane & 7;
    const uint32_t aOff = (uint32_t)((lrow + ((lane >> 3) & 1) * 8) * ROWB + (lane >> 4) * 16);
    const uint32_t bOff = (uint32_t)((lrow + (lane >> 4) * 8) * ROWB + ((lane >> 3) & 1) * 16);

    const int ldrow = t >> 2, ldch = t & 3;
    auto load_stage = [&](int kt, int slot) {
        const uint32_t sA = sbase + slot * STAGE_BYTES;
        const int k0 = kt * BK + ldch * 16;
        #pragma unroll
        for (int i = 0; i < 2; i++) {
            int row = ldrow + i * 64;
            CPA16(sA + row * ROWB + ldch * 16,
                  A + (size_t)(mBase + row) * K + k0);
            CPA16(sA + TILEB + row * ROWB + ldch * 16,
                  B + (size_t)(nBase + row) * K + k0);
        }
        CP_COMMIT();
    };

    load_stage(0, 0);
    load_stage(1, 1);
    load_stage(2, 2);
    load_stage(3, 3);

    for (int kt = 0; kt < kChunks; kt++) {
        CP_WAIT3();
        __syncthreads();
        const int nk = kt + 4;
        if (nk < kChunks) load_stage(nk, nk % STAGES);
        else CP_COMMIT();

        const uint32_t sA = sbase + (kt % STAGES) * STAGE_BYTES;
        const uint32_t sB = sA + TILEB;
        #pragma unroll
        for (int ks = 0; ks < 2; ks++) {
            uint32_t a[4][4], b[4][2];
            #pragma unroll
            for (int mi = 0; mi < 4; mi++)
                LDSM4(a[mi][0], a[mi][1], a[mi][2], a[mi][3],
                      sA + (wm * 64 + mi * 16) * ROWB + aOff + ks * 32);
            #pragma unroll
            for (int hf = 0; hf < 2; hf++) {
                uint32_t r0, r1, r2, r3;
                LDSM4(r0, r1, r2, r3,
                      sB + (wn * 32 + hf * 16) * ROWB + bOff + ks * 32);
                b[hf * 2][0] = r0; b[hf * 2][1] = r1;
                b[hf * 2 + 1][0] = r2; b[hf * 2 + 1][1] = r3;
            }
            #pragma unroll
            for (int mi = 0; mi < 4; mi++)
                #pragma unroll
                for (int ni = 0; ni < 4; ni++)
                    MMA_S8(acc[mi][ni], a[mi], b[ni]);
        }
    }

    #pragma unroll
    for (int mi = 0; mi < 4; mi++) {
        #pragma unroll
        for (int hf = 0; hf < 2; hf++) {
            const int row = mBase + wm * 64 + mi * 16 + hf * 8 + (lane >> 2);
            if (MODE == 1) {
                int rm = 0;
                #pragma unroll
                for (int ni = 0; ni < 4; ni++) {
                    int v0 = max(acc[mi][ni][hf * 2 + 0], 0);
                    int v1 = max(acc[mi][ni][hf * 2 + 1], 0);
                    rm = max(rm, max(v0, v1));
                    const int col = nBase + wn * 32 + ni * 8 + 2 * (lane & 3);
                    *(int2*)(outI + (size_t)row * ldo + col) = make_int2(v0, v1);
                }
                rm = max(rm, __shfl_xor_sync(0xffffffffu, rm, 1));
                rm = max(rm, __shfl_xor_sync(0xffffffffu, rm, 2));
                if ((lane & 3) == 0) atomicMax(&rowmax[row], rm);
            } else {
                const float s = d2[row];
                #pragma unroll
                for (int ni = 0; ni < 4; ni++) {
                    float v0 = (float)acc[mi][ni][hf * 2 + 0] * s;
                    float v1 = (float)acc[mi][ni][hf * 2 + 1] * s;
                    const int col = nBase + wn * 32 + ni * 8 + 2 * (lane & 3);
                    *(float2*)(outF + (size_t)row * ldo + col) = make_float2(v0, v1);
                }
            }
        }
    }
}

// ---------------- host: forked-stream capture ----------------
extern "C" void kernel_launch(void* const* d_in, const int* in_sizes, int n_in,
                              void* d_out, int out_size) {
    const float* x  = (const float*)d_in[0];
    const float* w1 = (const float*)d_in[1];
    const float* w2 = (const float*)d_in[2];
    float* out = (float*)d_out;

    void *p_xq, *p_w1q, *p_w2q, *p_hq, *p_ha, *p_d2, *p_rm;
    cudaGetSymbolAddress(&p_xq,  g_xq);
    cudaGetSymbolAddress(&p_w1q, g_w1q);
    cudaGetSymbolAddress(&p_w2q, g_w2q);
    cudaGetSymbolAddress(&p_hq,  g_hq);
    cudaGetSymbolAddress(&p_ha,  g_ha);
    cudaGetSymbolAddress(&p_d2,  g_d2);
    cudaGetSymbolAddress(&p_rm,  g_rowmax);

    cudaFuncSetAttribute(k_gemm<1>, cudaFuncAttributeMaxDynamicSharedMemorySize, GEMM_SMEM);
    cudaFuncSetAttribute(k_gemm<0>, cudaFuncAttributeMaxDynamicSharedMemorySize, GEMM_SMEM);

    cudaStream_t s2;
    cudaStreamCreateWithFlags(&s2, cudaStreamNonBlocking);
    cudaEvent_t evFork, evW1, evW2;
    cudaEventCreateWithFlags(&evFork, cudaEventDisableTiming);
    cudaEventCreateWithFlags(&evW1,   cudaEventDisableTiming);
    cudaEventCreateWithFlags(&evW2,   cudaEventDisableTiming);

    // fork: branch B (weights) on s2, branch A (activations) on stream 0
    cudaEventRecord(evFork, 0);
    cudaStreamWaitEvent(s2, evFork, 0);

    k_quantize_x<<<TOKENS, 256>>>(x);                               // A
    k_absmean<<<dim3(1024, 2), 256, 0, s2>>>(w1, w2);               // B
    k_finalize_gamma<<<2, 256, 0, s2>>>();                          // B
    k_quantize_w<<<4096, 256, 0, s2>>>(w1, 0);                      // B
    cudaEventRecord(evW1, s2);
    k_quantize_w<<<4096, 256, 0, s2>>>(w2, 1);                      // B (overlaps gemm1)
    cudaEventRecord(evW2, s2);

    cudaStreamWaitEvent(0, evW1, 0);                                // join: xq + w1q ready
    dim3 g1(DFF / BN, TOKENS / BM);
    k_gemm<1><<<g1, 256, GEMM_SMEM>>>((const int8_t*)p_xq, (const int8_t*)p_w1q,
                                      DMODEL, DFF,
                                      (int*)p_ha, nullptr, (int*)p_rm, nullptr);

    k_quantize_h<<<TOKENS, 256>>>();

    cudaStreamWaitEvent(0, evW2, 0);                                // join: w2q ready
    dim3 g2(DMODEL / BN, TOKENS / BM);
    k_gemm<0><<<g2, 256, GEMM_SMEM>>>((const int8_t*)p_hq, (const int8_t*)p_w2q,
                                      DFF, DMODEL,
                                      nullptr, out, nullptr, (const float*)p_d2);

    cudaEventDestroy(evFork);
    cudaEventDestroy(evW1);
    cudaEventDestroy(evW2);
    cudaStreamDestroy(s2);
}